// round 15
// baseline (speedup 1.0000x reference)
#include <cuda_runtime.h>
#include <cuda_bf16.h>
#include <cstdint>

// B=16, H=90, LP=512, W*L=65536, K=384
// out = mean_{b,h,j} (cs[b,h,j] - cs_p[b,h,pos[b,j]])^2
// pos[b] = ascending indices where mask[b]==1 (exactly K per batch).

#define B_      16
#define H_      90
#define LP_     512
#define WL_     65536
#define K_      384
#define HB_     3                    // heads per gatherer block
#define QPH_    (K_ / 4)             // 96 quad-columns per head
#define NT_     (HB_ * QPH_)         // 288 threads per gatherer block
#define GPB_    (H_ / HB_)           // 30 gatherer blocks per batch
#define NGATH_  (B_ * GPB_)          // 480 gatherer blocks
#define SEG_    16                   // segments per batch
#define SEGSZ_  (WL_ / SEG_)         // 4096 mask ints per segment
#define NSCAN_  (B_ * SEG_)          // 256 scanner blocks
#define NWARP_  (NT_ / 32)           // 9 warps per gatherer block

__device__ int      g_pos_seg[B_ * SEG_ * K_];   // seg-local ascending positions
__device__ unsigned g_cnt[B_ * SEG_];            // ones per segment

// evict_last loads: keep the ~75MB hot set L2-resident across graph replays
__device__ __forceinline__ float ldg_el_f32(const float* p) {
    float v;
    asm("{\n\t"
        ".reg .b64 pol;\n\t"
        "createpolicy.fractional.L2::evict_last.b64 pol, 1.0;\n\t"
        "ld.global.nc.L2::cache_hint.f32 %0, [%1], pol;\n\t"
        "}"
        : "=f"(v) : "l"(p));
    return v;
}

__device__ __forceinline__ int4 ldg_el_int4(const int4* p) {
    int4 v;
    asm("{\n\t"
        ".reg .b64 pol;\n\t"
        "createpolicy.fractional.L2::evict_last.b64 pol, 1.0;\n\t"
        "ld.global.nc.L2::cache_hint.v4.b32 {%0,%1,%2,%3}, [%4], pol;\n\t"
        "}"
        : "=r"(v.x), "=r"(v.y), "=r"(v.z), "=r"(v.w) : "l"(p));
    return v;
}

__device__ __forceinline__ float4 ldg_el_f32x4(const float4* p) {
    float4 v;
    asm("{\n\t"
        ".reg .b64 pol;\n\t"
        "createpolicy.fractional.L2::evict_last.b64 pol, 1.0;\n\t"
        "ld.global.nc.L2::cache_hint.v4.f32 {%0,%1,%2,%3}, [%4], pol;\n\t"
        "}"
        : "=f"(v.x), "=f"(v.y), "=f"(v.z), "=f"(v.w) : "l"(p));
    return v;
}

// coherent L2 loads for data written by the primary grid
__device__ __forceinline__ int ldg_cg_s32(const int* p) {
    int v;
    asm volatile("ld.global.cg.s32 %0, [%1];" : "=r"(v) : "l"(p));
    return v;
}
__device__ __forceinline__ unsigned ldg_cg_u32(const unsigned* p) {
    unsigned v;
    asm volatile("ld.global.cg.u32 %0, [%1];" : "=r"(v) : "l"(p));
    return v;
}

// ---------------------------------------------------------------------------
// PRIMARY: 256 blocks x 512 threads. Block (b, s) scans segment s of batch b
// (4096 ints, 2 int4/thread) and publishes SEGMENT-LOCAL positions + count.
// No cross-block communication; full-chip parallel. Triggers PDL at the end.
// ---------------------------------------------------------------------------
__global__ void __launch_bounds__(512) scan_kernel(
    const int* __restrict__ mask, float* __restrict__ out)
{
    const int t    = threadIdx.x;
    const int lane = t & 31;
    const int wid  = t >> 5;                      // 0..15
    const int b    = blockIdx.x / SEG_;
    const int s    = blockIdx.x % SEG_;

    if (blockIdx.x == 0 && t == 0) out[0] = 0.0f;   // d_out poisoned

    __shared__ int warpsums[16];

    // pack: 2 int4 = 8 ints per thread -> 8 bits
    const int4* mb = reinterpret_cast<const int4*>(
        mask + (size_t)b * WL_ + s * SEGSZ_) + t * 2;
    const int4 v0 = ldg_el_int4(mb + 0);
    const int4 v1 = ldg_el_int4(mb + 1);
    unsigned bits = (unsigned)(v0.x != 0)
                  | ((unsigned)(v0.y != 0) << 1)
                  | ((unsigned)(v0.z != 0) << 2)
                  | ((unsigned)(v0.w != 0) << 3)
                  | ((unsigned)(v1.x != 0) << 4)
                  | ((unsigned)(v1.y != 0) << 5)
                  | ((unsigned)(v1.z != 0) << 6)
                  | ((unsigned)(v1.w != 0) << 7);

    // block scan of popcounts
    const int cnt = __popc(bits);
    int inc = cnt;
#pragma unroll
    for (int o = 1; o < 32; o <<= 1) {
        int y = __shfl_up_sync(0xffffffffu, inc, o);
        if (lane >= o) inc += y;
    }
    if (lane == 31) warpsums[wid] = inc;
    __syncthreads();
    if (wid == 0 && lane < 16) {
        int y = warpsums[lane];
#pragma unroll
        for (int o = 1; o < 16; o <<= 1) {
            int z = __shfl_up_sync(0x0000ffffu, y, o);
            if (lane >= o) y += z;
        }
        warpsums[lane] = y;
    }
    __syncthreads();

    int off = (inc - cnt) + (wid > 0 ? warpsums[wid - 1] : 0);

    int* posb = g_pos_seg + (size_t)(b * SEG_ + s) * K_;
    const int base = s * SEGSZ_ + t * 8;          // GLOBAL position of bit 0
    unsigned x = bits;
    while (x) {
        const int i = __ffs(x) - 1;
        posb[off++] = base + i;
        x &= x - 1;
    }
    if (t == 0)
        g_cnt[b * SEG_ + s] = (unsigned)warpsums[15];

    __threadfence();
    __syncthreads();
    cudaTriggerProgrammaticLaunchCompletion();
}

// ---------------------------------------------------------------------------
// SECONDARY (PDL): 480 blocks x 288 threads. Thread t owns head t/96 and
// quad-column t%96 (4 consecutive columns): ONE float4 cs load + 4
// independent gathers. Preamble overlaps the primary; after
// cudaGridDependencySynchronize(): warp 0 prefix-sums the 16 segment counts,
// threads reassemble spos[384] (two guarded rounds of 288), gather, reduce.
// ---------------------------------------------------------------------------
__global__ void __launch_bounds__(NT_) mse_kernel(
    const float* __restrict__ cs, const float* __restrict__ cs_p,
    float* __restrict__ out)
{
    const int blk = blockIdx.x;                   // 0 .. 479
    const int b   = blk / GPB_;
    const int h0  = (blk % GPB_) * HB_;
    const int t   = threadIdx.x;                  // 0 .. 287
    const int lane = t & 31;
    const int wid  = t >> 5;                      // 0..8
    const int h    = t / QPH_;                    // 0..2
    const int q    = t - h * QPH_;                // 0..95

    __shared__ int   pfx[SEG_];                   // exclusive prefix of counts
    __shared__ int   spos[K_];
    __shared__ float wsum[NWARP_];

    const size_t bh = (size_t)(b * H_ + h0 + h);

    // p-independent preamble: one float4 cs load, overlaps the scanner
    const float4 a = ldg_el_f32x4(
        reinterpret_cast<const float4*>(cs + bh * LP_) + q);

    // HW wait for the primary grid
    cudaGridDependencySynchronize();

    // warp 0: prefix-sum the 16 segment counts
    if (wid == 0) {
        int c = (lane < SEG_) ? (int)ldg_cg_u32(g_cnt + b * SEG_ + lane) : 0;
        int incl = c;
#pragma unroll
        for (int o = 1; o < 16; o <<= 1) {
            int y = __shfl_up_sync(0xffffffffu, incl, o);
            if (lane >= o) incl += y;
        }
        if (lane < SEG_) pfx[lane] = incl - c;    // exclusive prefix
    }
    __syncthreads();

    // reassemble spos[0..383] in two guarded rounds of 288 threads
#pragma unroll
    for (int rr = 0; rr < 2; rr++) {
        const int j = t + rr * NT_;
        if (j < K_) {
            int s = 0;
#pragma unroll
            for (int k = 1; k < SEG_; k++)
                s += (j >= pfx[k]);
            spos[j] = ldg_cg_s32(
                g_pos_seg + (size_t)(b * SEG_ + s) * K_ + (j - pfx[s]));
        }
    }
    __syncthreads();

    // 4 independent gathers per thread (columns 4q .. 4q+3 of head h)
    const float* cspb = cs_p + bh * WL_;
    const float c0 = ldg_el_f32(cspb + spos[4 * q + 0]);
    const float c1 = ldg_el_f32(cspb + spos[4 * q + 1]);
    const float c2 = ldg_el_f32(cspb + spos[4 * q + 2]);
    const float c3 = ldg_el_f32(cspb + spos[4 * q + 3]);

    const float d0 = a.x - c0, d1 = a.y - c1, d2 = a.z - c2, d3 = a.w - c3;
    float sacc = fmaf(d0, d0, fmaf(d1, d1, fmaf(d2, d2, d3 * d3)));

    // block reduce (9 warps)
#pragma unroll
    for (int o = 16; o > 0; o >>= 1)
        sacc += __shfl_down_sync(0xffffffffu, sacc, o);
    if (lane == 0) wsum[wid] = sacc;
    __syncthreads();

    if (wid == 0) {
        float v = (lane < NWARP_) ? wsum[lane] : 0.0f;
#pragma unroll
        for (int o = 8; o > 0; o >>= 1)
            v += __shfl_down_sync(0xffffffffu, v, o);
        if (lane == 0) {
            const float scale = 1.0f / ((float)B_ * (float)H_ * (float)K_);
            atomicAdd(out, v * scale);
        }
    }
}

extern "C" void kernel_launch(void* const* d_in, const int* in_sizes, int n_in,
                              void* d_out, int out_size)
{
    const float* cs   = (const float*)d_in[0];  // (B, H, LP)
    const float* cs_p = (const float*)d_in[1];  // (B, H, W, L)
    const int*   mask = (const int*)d_in[2];    // (B, W, L)
    float* out = (float*)d_out;

    // primary: segmented scan, full-chip parallel
    scan_kernel<<<NSCAN_, 512>>>(mask, out);

    // secondary with programmatic dependent launch (overlaps primary)
    cudaLaunchConfig_t cfg = {};
    cfg.gridDim  = dim3(NGATH_);
    cfg.blockDim = dim3(NT_);
    cfg.dynamicSmemBytes = 0;
    cfg.stream = 0;
    cudaLaunchAttribute attr[1];
    attr[0].id = cudaLaunchAttributeProgrammaticStreamSerialization;
    attr[0].val.programmaticStreamSerializationAllowed = 1;
    cfg.attrs = attr;
    cfg.numAttrs = 1;
    cudaLaunchKernelEx(&cfg, mse_kernel, cs, cs_p, out);
}

// round 16
// speedup vs baseline: 1.0025x; 1.0025x over previous
#include <cuda_runtime.h>
#include <cuda_bf16.h>
#include <cstdint>

// B=16, H=90, LP=512, W*L=65536, K=384
// out = mean_{b,h,j} (cs[b,h,j] - cs_p[b,h,pos[b,j]])^2
// pos[b] = ascending indices where mask[b]==1 (exactly K per batch).

#define B_      16
#define H_      90
#define LP_     512
#define WL_     65536
#define K_      384
#define HB_     2                    // heads per gatherer block
#define GPB_    (H_ / HB_)           // 45 gatherer blocks per batch
#define NGATH_  (B_ * GPB_)          // 720 gatherer blocks
#define SEG_    16                   // segments per batch
#define SEGSZ_  (WL_ / SEG_)         // 4096 mask ints per segment
#define NSCAN_  (B_ * SEG_)          // 256 scanner blocks

__device__ int      g_pos_seg[B_ * SEG_ * K_];   // seg-local ascending positions
__device__ unsigned g_cnt[B_ * SEG_];            // ones per segment

// evict_last loads: keep the ~75MB hot set L2-resident across graph replays
__device__ __forceinline__ float ldg_el_f32(const float* p) {
    float v;
    asm("{\n\t"
        ".reg .b64 pol;\n\t"
        "createpolicy.fractional.L2::evict_last.b64 pol, 1.0;\n\t"
        "ld.global.nc.L2::cache_hint.f32 %0, [%1], pol;\n\t"
        "}"
        : "=f"(v) : "l"(p));
    return v;
}

__device__ __forceinline__ int4 ldg_el_int4(const int4* p) {
    int4 v;
    asm("{\n\t"
        ".reg .b64 pol;\n\t"
        "createpolicy.fractional.L2::evict_last.b64 pol, 1.0;\n\t"
        "ld.global.nc.L2::cache_hint.v4.b32 {%0,%1,%2,%3}, [%4], pol;\n\t"
        "}"
        : "=r"(v.x), "=r"(v.y), "=r"(v.z), "=r"(v.w) : "l"(p));
    return v;
}

// coherent L2 loads for data written by the primary grid
__device__ __forceinline__ int ldg_cg_s32(const int* p) {
    int v;
    asm volatile("ld.global.cg.s32 %0, [%1];" : "=r"(v) : "l"(p));
    return v;
}
__device__ __forceinline__ unsigned ldg_cg_u32(const unsigned* p) {
    unsigned v;
    asm volatile("ld.global.cg.u32 %0, [%1];" : "=r"(v) : "l"(p));
    return v;
}

// ---------------------------------------------------------------------------
// PRIMARY: 256 blocks x 512 threads. Block (b, s) scans segment s of batch b
// (4096 ints, 2 int4/thread) and publishes SEGMENT-LOCAL positions + count.
// No cross-block communication; full-chip parallel. Triggers PDL at the end.
// ---------------------------------------------------------------------------
__global__ void __launch_bounds__(512) scan_kernel(
    const int* __restrict__ mask, float* __restrict__ out)
{
    const int t    = threadIdx.x;
    const int lane = t & 31;
    const int wid  = t >> 5;                      // 0..15
    const int b    = blockIdx.x / SEG_;
    const int s    = blockIdx.x % SEG_;

    if (blockIdx.x == 0 && t == 0) out[0] = 0.0f;   // d_out poisoned

    __shared__ int warpsums[16];

    // pack: 2 int4 = 8 ints per thread -> 8 bits
    const int4* mb = reinterpret_cast<const int4*>(
        mask + (size_t)b * WL_ + s * SEGSZ_) + t * 2;
    const int4 v0 = ldg_el_int4(mb + 0);
    const int4 v1 = ldg_el_int4(mb + 1);
    unsigned bits = (unsigned)(v0.x != 0)
                  | ((unsigned)(v0.y != 0) << 1)
                  | ((unsigned)(v0.z != 0) << 2)
                  | ((unsigned)(v0.w != 0) << 3)
                  | ((unsigned)(v1.x != 0) << 4)
                  | ((unsigned)(v1.y != 0) << 5)
                  | ((unsigned)(v1.z != 0) << 6)
                  | ((unsigned)(v1.w != 0) << 7);

    // block scan of popcounts
    const int cnt = __popc(bits);
    int inc = cnt;
#pragma unroll
    for (int o = 1; o < 32; o <<= 1) {
        int y = __shfl_up_sync(0xffffffffu, inc, o);
        if (lane >= o) inc += y;
    }
    if (lane == 31) warpsums[wid] = inc;
    __syncthreads();
    if (wid == 0 && lane < 16) {
        int y = warpsums[lane];
#pragma unroll
        for (int o = 1; o < 16; o <<= 1) {
            int z = __shfl_up_sync(0x0000ffffu, y, o);
            if (lane >= o) y += z;
        }
        warpsums[lane] = y;
    }
    __syncthreads();

    int off = (inc - cnt) + (wid > 0 ? warpsums[wid - 1] : 0);

    int* posb = g_pos_seg + (size_t)(b * SEG_ + s) * K_;
    const int base = s * SEGSZ_ + t * 8;          // GLOBAL position of bit 0
    unsigned x = bits;
    while (x) {
        const int i = __ffs(x) - 1;
        posb[off++] = base + i;
        x &= x - 1;
    }
    if (t == 0)
        g_cnt[b * SEG_ + s] = (unsigned)warpsums[15];

    __threadfence();
    __syncthreads();
    cudaTriggerProgrammaticLaunchCompletion();
}

// ---------------------------------------------------------------------------
// SECONDARY (PDL): 720 blocks x 384 threads (HB_=2 heads per block).
// Preamble (cs preload) overlaps the primary; after
// cudaGridDependencySynchronize(): warp 0 prefix-sums the 16 segment counts,
// thread j reassembles its global rank -> position, gathers HB_ heads,
// block reduce, atomicAdd.
// ---------------------------------------------------------------------------
__global__ void __launch_bounds__(K_) mse_kernel(
    const float* __restrict__ cs, const float* __restrict__ cs_p,
    float* __restrict__ out)
{
    const int blk = blockIdx.x;                   // 0 .. NGATH_-1
    const int b   = blk / GPB_;
    const int h0  = (blk % GPB_) * HB_;
    const int j   = threadIdx.x;                  // 0 .. 383
    const int lane = j & 31;
    const int wid  = j >> 5;

    __shared__ int   pfx[SEG_];                   // exclusive prefix of counts
    __shared__ float wsum[12];

    const float* csb = cs + ((size_t)(b * H_ + h0)) * LP_ + j;

    // p-independent preamble: overlaps the scanner
    float a[HB_];
#pragma unroll
    for (int r = 0; r < HB_; r++) a[r] = __ldg(csb + (size_t)r * LP_);

    // HW wait for the primary grid
    cudaGridDependencySynchronize();

    // warp 0: prefix-sum the 16 segment counts
    if (wid == 0) {
        int c = (lane < SEG_) ? (int)ldg_cg_u32(g_cnt + b * SEG_ + lane) : 0;
        int incl = c;
#pragma unroll
        for (int o = 1; o < 16; o <<= 1) {
            int y = __shfl_up_sync(0xffffffffu, incl, o);
            if (lane >= o) incl += y;
        }
        if (lane < SEG_) pfx[lane] = incl - c;    // exclusive prefix
    }
    __syncthreads();

    // locate segment: s = max { k : pfx[k] <= j }
    int s = 0;
#pragma unroll
    for (int k = 1; k < SEG_; k++)
        s += (j >= pfx[k]);

    const int p = ldg_cg_s32(g_pos_seg + (size_t)(b * SEG_ + s) * K_ + (j - pfx[s]));
    const float* cspb = cs_p + ((size_t)(b * H_ + h0)) * WL_ + p;

    float c[HB_];
#pragma unroll
    for (int r = 0; r < HB_; r++) c[r] = ldg_el_f32(cspb + (size_t)r * WL_);

    float sacc = 0.0f;
#pragma unroll
    for (int r = 0; r < HB_; r++) { float d = a[r] - c[r]; sacc = fmaf(d, d, sacc); }

    // block reduce (12 warps)
#pragma unroll
    for (int o = 16; o > 0; o >>= 1)
        sacc += __shfl_down_sync(0xffffffffu, sacc, o);
    if (lane == 0) wsum[wid] = sacc;
    __syncthreads();

    if (wid == 0) {
        float v = (lane < 12) ? wsum[lane] : 0.0f;
#pragma unroll
        for (int o = 16; o > 0; o >>= 1)
            v += __shfl_down_sync(0xffffffffu, v, o);
        if (lane == 0) {
            const float scale = 1.0f / ((float)B_ * (float)H_ * (float)K_);
            atomicAdd(out, v * scale);
        }
    }
}

extern "C" void kernel_launch(void* const* d_in, const int* in_sizes, int n_in,
                              void* d_out, int out_size)
{
    const float* cs   = (const float*)d_in[0];  // (B, H, LP)
    const float* cs_p = (const float*)d_in[1];  // (B, H, W, L)
    const int*   mask = (const int*)d_in[2];    // (B, W, L)
    float* out = (float*)d_out;

    // primary: segmented scan, full-chip parallel
    scan_kernel<<<NSCAN_, 512>>>(mask, out);

    // secondary with programmatic dependent launch (overlaps primary)
    cudaLaunchConfig_t cfg = {};
    cfg.gridDim  = dim3(NGATH_);
    cfg.blockDim = dim3(K_);
    cfg.dynamicSmemBytes = 0;
    cfg.stream = 0;
    cudaLaunchAttribute attr[1];
    attr[0].id = cudaLaunchAttributeProgrammaticStreamSerialization;
    attr[0].val.programmaticStreamSerializationAllowed = 1;
    cfg.attrs = attr;
    cfg.numAttrs = 1;
    cudaLaunchKernelEx(&cfg, mse_kernel, cs, cs_p, out);
}